// round 14
// baseline (speedup 1.0000x reference)
#include <cuda_runtime.h>
#include <math.h>

#define NT   65536
#define NCH  148
#define WUP  64
#define TT   64

// Scratch (allocation-free __device__ globals), padded by TT tokens so tile
// prefetch may harmlessly overrun the last chunk boundary.
// g_ddx[(n,d)] = (dt, dt*xb, silu(z), D*xb) ; g_bc[(n,s)] = (B, C).
__device__ float4 g_ddx[(NT + TT) * 16];
__device__ float2 g_bc [(NT + TT) * 16];
__device__ float  g_hdump[256];

// Dynamic smem layout for scan (bytes):
//   [0, 49152)        sbuf : 2 x TT x (16 ddx float4 + 8 bc float4)
//   [49152, 114688)   hc   : TT x 256 floats (h*C per step, per (d,s))
//   [114688, 118784)  syf  : TT x 16 floats (gated y)
//   [118784, 119296)  sw   : Wout 128 floats
#define SMEM_SCAN 119296

// ---------------------------------------------------------------------------
// Kernel 1: projections, FOUR threads per token (r = g&3 handles channels
// j = 4r..4r+3). 8192 warps -> latency fully hidden; weight LDGs are 4-way
// dedup'd per warp; xb shared within the 4-lane group via 16 shuffles.
// ---------------------------------------------------------------------------
__global__ __launch_bounds__(256) void precompute_kernel(
    const float* __restrict__ x,
    const float* __restrict__ in_w,   // (32,8)
    const float* __restrict__ dt_w,   // (16,16)
    const float* __restrict__ dt_b,   // (16,)
    const float* __restrict__ B_w,    // (16,16)
    const float* __restrict__ C_w,    // (16,16)
    const float* __restrict__ Dp)     // (16,)
{
    const unsigned FULL = 0xffffffffu;
    int g  = blockIdx.x * 256 + threadIdx.x;
    int n  = g >> 2;
    int r  = g & 3;
    int gb = (threadIdx.x & 31) & ~3;        // group base lane

    const float4* xp = (const float4*)x;
    float4 xa = xp[n * 2 + 0];
    float4 xc = xp[n * 2 + 1];
    float xv[8] = {xa.x, xa.y, xa.z, xa.w, xc.x, xc.y, xc.z, xc.w};

    // Phase 1: my 4 channels of xb and z.
    const float4* w4 = (const float4*)in_w;
    float xb4[4], z4[4];
#pragma unroll
    for (int q = 0; q < 4; q++) {
        int j = r * 4 + q;
        float4 a0 = __ldg(w4 + j * 2),        a1 = __ldg(w4 + j * 2 + 1);
        float4 b0 = __ldg(w4 + (j + 16) * 2), b1 = __ldg(w4 + (j + 16) * 2 + 1);
        float a = a0.x * xv[0];
        a = fmaf(a0.y, xv[1], a); a = fmaf(a0.z, xv[2], a); a = fmaf(a0.w, xv[3], a);
        a = fmaf(a1.x, xv[4], a); a = fmaf(a1.y, xv[5], a);
        a = fmaf(a1.z, xv[6], a); a = fmaf(a1.w, xv[7], a);
        float b = b0.x * xv[0];
        b = fmaf(b0.y, xv[1], b); b = fmaf(b0.z, xv[2], b); b = fmaf(b0.w, xv[3], b);
        b = fmaf(b1.x, xv[4], b); b = fmaf(b1.y, xv[5], b);
        b = fmaf(b1.z, xv[6], b); b = fmaf(b1.w, xv[7], b);
        xb4[q] = a;
        z4[q]  = b;
    }

    // Share all 16 xb values within the 4-lane token group.
    float xg[16];
#pragma unroll
    for (int i = 0; i < 16; i++)
        xg[i] = __shfl_sync(FULL, xb4[i & 3], gb + (i >> 2));

    // Phase 2: dt/B/C rows for my 4 channels + activations.
    const float4* dw4 = (const float4*)dt_w;
    const float4* bw4 = (const float4*)B_w;
    const float4* cw4 = (const float4*)C_w;
#pragma unroll
    for (int q = 0; q < 4; q++) {
        int j = r * 4 + q;
        float dacc = __ldg(dt_b + j), bacc = 0.f, cacc = 0.f;
#pragma unroll
        for (int p = 0; p < 4; p++) {
            float4 wd = __ldg(dw4 + j * 4 + p);
            float4 wb = __ldg(bw4 + j * 4 + p);
            float4 wc = __ldg(cw4 + j * 4 + p);
            dacc = fmaf(wd.x, xg[p*4+0], dacc); dacc = fmaf(wd.y, xg[p*4+1], dacc);
            dacc = fmaf(wd.z, xg[p*4+2], dacc); dacc = fmaf(wd.w, xg[p*4+3], dacc);
            bacc = fmaf(wb.x, xg[p*4+0], bacc); bacc = fmaf(wb.y, xg[p*4+1], bacc);
            bacc = fmaf(wb.z, xg[p*4+2], bacc); bacc = fmaf(wb.w, xg[p*4+3], bacc);
            cacc = fmaf(wc.x, xg[p*4+0], cacc); cacc = fmaf(wc.y, xg[p*4+1], cacc);
            cacc = fmaf(wc.z, xg[p*4+2], cacc); cacc = fmaf(wc.w, xg[p*4+3], cacc);
        }
        float dt = __logf(1.0f + __expf(dacc));          // softplus (bounded arg)
        float zh = 0.5f * z4[q];
        float th;
        asm("tanh.approx.f32 %0, %1;" : "=f"(th) : "f"(zh));
        float gz  = fmaf(zh, th, zh);                    // silu(z)
        float Dxb = __ldg(Dp + j) * xb4[q];
        g_ddx[n * 16 + j] = make_float4(dt, dt * xb4[q], gz, Dxb);
        g_bc [n * 16 + j] = make_float2(bacc, cacc);
    }
}

// ---------------------------------------------------------------------------
// Kernel 2: chunked scan (64-step warmup; |A_bar|<1 contraction) with fused
// gate + output projection in a per-tile epilogue. One CTA per SM.
// Thread (d,s): d = tid>>4, s = tid&15. Step loop: 2 LDS.64, 1 SHFL, 1 MUFU
// (rcp), Taylor sincos (small angle: |dt*rope| < ~0.1), 1 STS of h*C.
// ---------------------------------------------------------------------------
__global__ __launch_bounds__(256) void scan_kernel(
    const float* __restrict__ A_log,  // (16,16) [d][s]
    const float* __restrict__ rope,   // (16,16) [d][s]
    const float* __restrict__ h0,     // (16,16) [d][s]
    const float* __restrict__ Wout,   // (8,16)
    float* __restrict__ out,          // (NT,8)
    float* __restrict__ hfin)         // 256 floats or nullptr
{
    extern __shared__ __align__(16) char smem_raw[];
    float4* sbuf = (float4*)smem_raw;                    // [2][1536]
    float*  hc   = (float*)(smem_raw + 49152);           // [TT*256]
    float*  syf  = (float*)(smem_raw + 114688);          // [TT*16]
    float*  sw   = (float*)(smem_raw + 118784);          // [128]

    const unsigned FULL = 0xffffffffu;
    int tid  = threadIdx.x;
    int d    = tid >> 4;
    int s    = tid & 15;
    int lane = tid & 31;
    int srcPrev = (lane & 16) | ((s + 15) & 15);

    if (tid < 128) sw[tid] = Wout[tid];

    int k     = blockIdx.x;
    int start = (int)(((long long)k       * NT) / NCH);
    int end   = (int)(((long long)(k + 1) * NT) / NCH);
    int begin = (k == 0) ? 0 : (start - WUP);

    float mAh = 0.5f * __expf(A_log[tid]);   // -A/2 > 0 ; den = 1 + dt*(-A/2)
    float rf  = rope[tid];
    float h   = (k == 0) ? h0[tid] : 0.0f;

    int nsteps = end - begin;
    int ntiles = (nsteps + TT - 1) / TT;

    {   // prologue: tile 0 (1536 float4 cooperative copy, 6 per thread)
#pragma unroll
        for (int q = 0; q < 6; q++) {
            int idx = q * 256 + tid;
            float4 v = (idx < 1024) ? g_ddx[(long)begin * 16 + idx]
                                    : ((const float4*)g_bc)[(long)begin * 8 + (idx - 1024)];
            sbuf[idx] = v;
        }
    }
    __syncthreads();

    for (int tl = 0; tl < ntiles; ++tl) {
        int cur = tl & 1;
        float4 pf[6];
        if (tl + 1 < ntiles) {        // next-tile LDGs land during compute
            long t0 = (long)(begin + (tl + 1) * TT);
#pragma unroll
            for (int q = 0; q < 6; q++) {
                int idx = q * 256 + tid;
                pf[q] = (idx < 1024) ? g_ddx[t0 * 16 + idx]
                                     : ((const float4*)g_bc)[t0 * 8 + (idx - 1024)];
            }
        }
        const float4* sdd = &sbuf[cur * 1536];
        const float2* sbc = (const float2*)(&sbuf[cur * 1536 + 1024]);
        int n0   = begin + tl * TT;
        int tmax = min(TT, end - n0);
        int lim1 = min(max(start - n0, 0), tmax);   // warmup steps in this tile
        int i    = 0;

#pragma unroll 4
        for (; i < lim1; i++) {       // warmup: no output
            float2 dd = *(const float2*)(sdd + i * 16 + d);   // (dt, dt*xb)
            float2 bc = sbc[i * 16 + s];
            float den = fmaf(dd.x, mAh, 1.0f);
            float rcp;
            asm("rcp.approx.ftz.f32 %0, %1;" : "=f"(rcp) : "f"(den));
            float Abar = fmaf(2.0f, rcp, -1.0f);              // (1+t)/(1-t)
            float a  = dd.x * rf;
            float a2 = a * a;
            float sn = a * fmaf(a2, -0.16666667f, 1.0f);
            float cs = fmaf(a2, fmaf(a2, 0.041666667f, -0.5f), 1.0f);
            float hp = __shfl_sync(FULL, h, srcPrev);
            float hr = fmaf(cs, h, -(sn * hp));
            h = fmaf(Abar, hr, dd.y * bc.x);
        }

#pragma unroll 4
        for (; i < tmax; i++) {       // output region: also dump h*C to smem
            float2 dd = *(const float2*)(sdd + i * 16 + d);
            float2 bc = sbc[i * 16 + s];
            float den = fmaf(dd.x, mAh, 1.0f);
            float rcp;
            asm("rcp.approx.ftz.f32 %0, %1;" : "=f"(rcp) : "f"(den));
            float Abar = fmaf(2.0f, rcp, -1.0f);
            float a  = dd.x * rf;
            float a2 = a * a;
            float sn = a * fmaf(a2, -0.16666667f, 1.0f);
            float cs = fmaf(a2, fmaf(a2, 0.041666667f, -0.5f), 1.0f);
            float hp = __shfl_sync(FULL, h, srcPrev);
            float hr = fmaf(cs, h, -(sn * hp));
            h = fmaf(Abar, hr, dd.y * bc.x);
            hc[i * 256 + tid] = h * bc.y;                     // conflict-free STS
        }

        __syncthreads();              // steps done; hc complete; sbuf[cur^1] free
        if (tl + 1 < ntiles) {
#pragma unroll
            for (int q = 0; q < 6; q++) sbuf[(cur ^ 1) * 1536 + q * 256 + tid] = pf[q];
        }

        int nout = tmax - lim1;
        // Epilogue A: y = sum_s h*C ; gate: yf = y*silu(z) + D*xb
        for (int t = tid; t < (nout << 4); t += 256) {
            int ii = lim1 + (t >> 4);
            int dj = t & 15;
            const float4* hp4 = (const float4*)(hc + (ii << 8) + (dj << 4));
            float4 v0 = hp4[0], v1 = hp4[1], v2 = hp4[2], v3 = hp4[3];
            float p = ((v0.x + v0.y) + (v0.z + v0.w)) + ((v1.x + v1.y) + (v1.z + v1.w))
                    + ((v2.x + v2.y) + (v2.z + v2.w)) + ((v3.x + v3.y) + (v3.z + v3.w));
            float4 g = sdd[ii * 16 + dj];                     // .z = silu(z), .w = D*xb
            syf[(ii << 4) + dj] = fmaf(p, g.z, g.w);
        }
        __syncthreads();
        // Epilogue B: out = yf @ Wout.T (coalesced stores)
        for (int t = tid; t < (nout << 3); t += 256) {
            int ii = lim1 + (t >> 3);
            int m  = t & 7;
            const float* wr = sw + (m << 4);
            const float* yr = syf + (ii << 4);
            float acc = wr[0] * yr[0];
#pragma unroll
            for (int j = 1; j < 16; j++) acc = fmaf(wr[j], yr[j], acc);
            out[(long)(n0 + ii) * 8 + m] = acc;
        }
    }

    if (k == NCH - 1) {
        float* dst = hfin ? hfin : g_hdump;
        dst[tid] = h;                 // exact final state (warmup error ~e^-30)
    }
}

// ---------------------------------------------------------------------------
extern "C" void kernel_launch(void* const* d_in, const int* in_sizes, int n_in,
                              void* d_out, int out_size)
{
    const float* x    = (const float*)d_in[0];
    const float* h0   = (const float*)d_in[1];
    const float* inw  = (const float*)d_in[2];
    const float* dtw  = (const float*)d_in[3];
    const float* dtb  = (const float*)d_in[4];
    const float* Bw   = (const float*)d_in[5];
    const float* Cw   = (const float*)d_in[6];
    const float* Alog = (const float*)d_in[7];
    const float* Dp   = (const float*)d_in[8];
    const float* rope = (const float*)d_in[9];
    const float* Wout = (const float*)d_in[10];

    float* out  = (float*)d_out;
    float* hfin = (out_size >= NT * 8 + 256) ? (out + NT * 8) : nullptr;

    // Opt-in to >48KB dynamic smem (host-side attribute, not an allocation;
    // idempotent, capture-legal).
    cudaFuncSetAttribute(scan_kernel,
                         cudaFuncAttributeMaxDynamicSharedMemorySize, SMEM_SCAN);

    precompute_kernel<<<NT / 64, 256>>>(x, inw, dtw, dtb, Bw, Cw, Dp);
    scan_kernel<<<NCH, 256, SMEM_SCAN>>>(Alog, rope, h0, Wout, out, hfin);
}

// round 15
// speedup vs baseline: 1.2123x; 1.2123x over previous
#include <cuda_runtime.h>
#include <math.h>

#define NT   65536
#define NCH  592          // 4 chunks per SM (148 SMs)
#define WUP  48           // warmup steps: decay ~e^-34 << 1e-3 tolerance
#define TT   64           // tokens per tile

__device__ float g_hdump[256];

// ---------------------------------------------------------------------------
// Single fused kernel. Grid = NCH chunks, 4 CTAs/SM. Per 64-token tile:
//   phase P1: stage x tile in smem (coalesced)
//   phase P2: projections (4 threads/token, weights smem-resident)
//             -> s_dd (dt, dt*xb), s_bc (B, C), s_gate (silu(z), D*xb)
//   phase S : sequential scan, thread (d,s) = (tid>>4, tid&15); per step:
//             2 LDS.64, rcp MUFU, Taylor sincos (|dt*rope| < ~0.2),
//             1 SHFL rotation, 4 SHFL_XOR reduction, gated write to s_yf
//   phase E : out = yf @ Wout.T, coalesced stores
// No global scratch; chunk warmup from zero state (|A_bar|<1 contraction).
// ---------------------------------------------------------------------------
__global__ __launch_bounds__(256, 4) void fused_kernel(
    const float* __restrict__ x,      // (NT, 8)
    const float* __restrict__ h0,     // (16,16) [d][s]
    const float* __restrict__ in_w,   // (32, 8)
    const float* __restrict__ dt_w,   // (16,16)
    const float* __restrict__ dt_b,   // (16,)
    const float* __restrict__ B_w,    // (16,16)
    const float* __restrict__ C_w,    // (16,16)
    const float* __restrict__ A_log,  // (16,16) [d][s]
    const float* __restrict__ Dp,     // (16,)
    const float* __restrict__ rope,   // (16,16) [d][s]
    const float* __restrict__ Wout,   // (8,16)
    float* __restrict__ out,          // (NT, 8)
    float* __restrict__ hfin)         // 256 floats or nullptr
{
    __shared__ float  s_inw[32 * 9];        // padded stride 9 (bank-safe)
    __shared__ float  s_dtw[16 * 20];       // padded stride 20 (float4-ok)
    __shared__ float  s_bw [16 * 20];
    __shared__ float  s_cw [16 * 20];
    __shared__ float  s_dtb[16], s_Dp[16];
    __shared__ float  s_wo [8 * 17];        // padded stride 17
    __shared__ float  s_x  [TT * 9];        // x tile, stride 9
    __shared__ float  s_xbv[TT * 20];       // xb exchange, stride 20
    __shared__ float2 s_dd [TT * 16];       // (dt, dt*xb)   keyed [i][d]
    __shared__ float2 s_gt [TT * 16];       // (silu(z), D*xb) [i][d]
    __shared__ float2 s_bc [TT * 16];       // (B, C)        keyed [i][s]
    __shared__ float  s_yf [TT * 16];       // gated y       [i][d]

    const unsigned FULL = 0xffffffffu;
    int tid  = threadIdx.x;
    int d    = tid >> 4;
    int s    = tid & 15;
    int lane = tid & 31;
    int srcPrev = (lane & 16) | ((s + 15) & 15);

    // ---- load weights into smem once ----
    if (tid < 128) s_wo[(tid >> 4) * 17 + (tid & 15)] = Wout[tid];
    {
        int t = tid;
        if (t < 256) s_inw[(t >> 3) * 9 + (t & 7)] = in_w[t];
        s_dtw[(t >> 4) * 20 + (t & 15)] = dt_w[t];
        s_bw [(t >> 4) * 20 + (t & 15)] = B_w[t];
        s_cw [(t >> 4) * 20 + (t & 15)] = C_w[t];
        if (t < 16) { s_dtb[t] = dt_b[t]; s_Dp[t] = Dp[t]; }
    }

    int k     = blockIdx.x;
    int start = (int)(((long long)k       * NT) / NCH);
    int end   = (int)(((long long)(k + 1) * NT) / NCH);
    int begin = (k == 0) ? 0 : (start - WUP);

    float mAh = 0.5f * __expf(A_log[tid]);   // -A/2 > 0 ; den = 1 + dt*(-A/2)
    float rf  = rope[tid];
    float h   = (k == 0) ? h0[tid] : 0.0f;

    int nsteps = end - begin;
    int ntiles = (nsteps + TT - 1) / TT;

    // projection-role indices: 4 threads per token
    int tl4 = tid >> 2;          // token slot 0..63
    int r   = tid & 3;           // channel group: j = 4r..4r+3

    for (int tl = 0; tl < ntiles; ++tl) {
        int tb   = begin + tl * TT;
        int tmax = min(TT, end - tb);
        int lim1 = min(max(start - tb, 0), tmax);

        // ---- P1: stage x tile (coalesced; clamp tail reads) ----
        __syncthreads();   // prior tile fully consumed before overwriting smem
#pragma unroll
        for (int q = 0; q < 2; q++) {
            int idx = q * 256 + tid;                 // 0..511
            int tok = idx >> 3, ii = idx & 7;
            long gidx = (long)(tb + tok) * 8 + ii;
            if (gidx >= (long)NT * 8) gidx = (long)NT * 8 - 1;
            s_x[tok * 9 + ii] = x[gidx];
        }
        __syncthreads();

        // ---- P2a: xb, z for my 4 channels ----
        float xv[8];
#pragma unroll
        for (int i = 0; i < 8; i++) xv[i] = s_x[tl4 * 9 + i];
        float xb4[4], z4[4];
#pragma unroll
        for (int q = 0; q < 4; q++) {
            int j = r * 4 + q;
            const float* wa = s_inw + j * 9;
            const float* wz = s_inw + (j + 16) * 9;
            float a = wa[0] * xv[0], b = wz[0] * xv[0];
#pragma unroll
            for (int i = 1; i < 8; i++) {
                a = fmaf(wa[i], xv[i], a);
                b = fmaf(wz[i], xv[i], b);
            }
            xb4[q] = a;
            z4[q]  = b;
        }
        *(float4*)(s_xbv + tl4 * 20 + r * 4) =
            make_float4(xb4[0], xb4[1], xb4[2], xb4[3]);
        __syncthreads();

        // ---- P2b: dt/B/C + activations for my 4 channels ----
        float xg[16];
#pragma unroll
        for (int q = 0; q < 4; q++) {
            float4 v = *(const float4*)(s_xbv + tl4 * 20 + q * 4);
            xg[q*4+0] = v.x; xg[q*4+1] = v.y; xg[q*4+2] = v.z; xg[q*4+3] = v.w;
        }
#pragma unroll
        for (int q = 0; q < 4; q++) {
            int j = r * 4 + q;
            float dacc = s_dtb[j], bacc = 0.f, cacc = 0.f;
#pragma unroll
            for (int p = 0; p < 4; p++) {
                float4 wd = *(const float4*)(s_dtw + j * 20 + p * 4);
                float4 wb = *(const float4*)(s_bw  + j * 20 + p * 4);
                float4 wc = *(const float4*)(s_cw  + j * 20 + p * 4);
                dacc = fmaf(wd.x, xg[p*4+0], dacc); dacc = fmaf(wd.y, xg[p*4+1], dacc);
                dacc = fmaf(wd.z, xg[p*4+2], dacc); dacc = fmaf(wd.w, xg[p*4+3], dacc);
                bacc = fmaf(wb.x, xg[p*4+0], bacc); bacc = fmaf(wb.y, xg[p*4+1], bacc);
                bacc = fmaf(wb.z, xg[p*4+2], bacc); bacc = fmaf(wb.w, xg[p*4+3], bacc);
                cacc = fmaf(wc.x, xg[p*4+0], cacc); cacc = fmaf(wc.y, xg[p*4+1], cacc);
                cacc = fmaf(wc.z, xg[p*4+2], cacc); cacc = fmaf(wc.w, xg[p*4+3], cacc);
            }
            float dt = __logf(1.0f + __expf(dacc));      // softplus (bounded)
            float zh = 0.5f * z4[q];
            float th;
            asm("tanh.approx.f32 %0, %1;" : "=f"(th) : "f"(zh));
            float gz = fmaf(zh, th, zh);                 // silu(z)
            s_dd[tl4 * 16 + j] = make_float2(dt, dt * xb4[q]);
            s_gt[tl4 * 16 + j] = make_float2(gz, s_Dp[j] * xb4[q]);
            s_bc[tl4 * 16 + j] = make_float2(bacc, cacc);
        }
        __syncthreads();

        // ---- S: sequential scan over this tile ----
        int i = 0;
#pragma unroll 4
        for (; i < lim1; i++) {          // warmup: no output
            float2 dd = s_dd[i * 16 + d];
            float2 bc = s_bc[i * 16 + s];
            float den = fmaf(dd.x, mAh, 1.0f);
            float rcp;
            asm("rcp.approx.ftz.f32 %0, %1;" : "=f"(rcp) : "f"(den));
            float Abar = fmaf(2.0f, rcp, -1.0f);         // (1+t)/(1-t)
            float a  = dd.x * rf;
            float a2 = a * a;
            float sn = a * fmaf(a2, -0.16666667f, 1.0f);
            float cs = fmaf(a2, fmaf(a2, 0.041666667f, -0.5f), 1.0f);
            float hp = __shfl_sync(FULL, h, srcPrev);
            float hr = fmaf(cs, h, -(sn * hp));
            h = fmaf(Abar, hr, dd.y * bc.x);
        }
#pragma unroll 4
        for (; i < tmax; i++) {          // output region
            float2 dd = s_dd[i * 16 + d];
            float2 bc = s_bc[i * 16 + s];
            float den = fmaf(dd.x, mAh, 1.0f);
            float rcp;
            asm("rcp.approx.ftz.f32 %0, %1;" : "=f"(rcp) : "f"(den));
            float Abar = fmaf(2.0f, rcp, -1.0f);
            float a  = dd.x * rf;
            float a2 = a * a;
            float sn = a * fmaf(a2, -0.16666667f, 1.0f);
            float cs = fmaf(a2, fmaf(a2, 0.041666667f, -0.5f), 1.0f);
            float hp = __shfl_sync(FULL, h, srcPrev);
            float hr = fmaf(cs, h, -(sn * hp));
            h = fmaf(Abar, hr, dd.y * bc.x);

            float p = h * bc.y;
            p += __shfl_xor_sync(FULL, p, 1);
            p += __shfl_xor_sync(FULL, p, 2);
            p += __shfl_xor_sync(FULL, p, 4);
            p += __shfl_xor_sync(FULL, p, 8);
            if (s == 0) {
                float2 g = s_gt[i * 16 + d];
                s_yf[i * 16 + d] = fmaf(p, g.x, g.y);    // y*silu(z) + D*xb
            }
        }
        __syncthreads();

        // ---- E: out = yf @ Wout.T (coalesced stores) ----
        int nout = tmax - lim1;
        for (int t = tid; t < (nout << 3); t += 256) {
            int ii = lim1 + (t >> 3);
            int m  = t & 7;
            const float* wr = s_wo + m * 17;
            const float* yr = s_yf + (ii << 4);
            float acc = wr[0] * yr[0];
#pragma unroll
            for (int j = 1; j < 16; j++) acc = fmaf(wr[j], yr[j], acc);
            out[(long)(tb + ii) * 8 + m] = acc;
        }
    }

    if (k == NCH - 1) {
        float* dst = hfin ? hfin : g_hdump;
        dst[tid] = h;                    // exact final state (warmup err ~e^-34)
    }
}

// ---------------------------------------------------------------------------
extern "C" void kernel_launch(void* const* d_in, const int* in_sizes, int n_in,
                              void* d_out, int out_size)
{
    const float* x    = (const float*)d_in[0];
    const float* h0   = (const float*)d_in[1];
    const float* inw  = (const float*)d_in[2];
    const float* dtw  = (const float*)d_in[3];
    const float* dtb  = (const float*)d_in[4];
    const float* Bw   = (const float*)d_in[5];
    const float* Cw   = (const float*)d_in[6];
    const float* Alog = (const float*)d_in[7];
    const float* Dp   = (const float*)d_in[8];
    const float* rope = (const float*)d_in[9];
    const float* Wout = (const float*)d_in[10];

    float* out  = (float*)d_out;
    float* hfin = (out_size >= NT * 8 + 256) ? (out + NT * 8) : nullptr;

    fused_kernel<<<NCH, 256>>>(x, h0, inw, dtw, dtb, Bw, Cw,
                               Alog, Dp, rope, Wout, out, hfin);
}

// round 17
// speedup vs baseline: 1.5399x; 1.2703x over previous
#include <cuda_runtime.h>
#include <math.h>

#define NT   65536
#define NCH  592          // 4 chunks per SM (148 SMs)
#define WUP  48           // warmup steps: decay ~e^-34 << 1e-3 tolerance
#define TT   32           // tokens per tile

__device__ float g_hdump[256];

// ---------------------------------------------------------------------------
// Single fused kernel, 4 CTAs/SM. Scan uses 128 threads with TWO states each
// (d = tid>>3, sp = tid&7 owns s = 2sp, 2sp+1):
//   - 1 rotation SHFL per state-pair (odd state's neighbor is own even state)
//   - no reduction shuffles: per-step partial p = he*Ce + ho*Co goes to smem
//     (1 STS), reduced in a parallel per-tile epilogue
//   - per warp-step MIO: LDS.64(dd) + LDS.128(bc) + SHFL + STS = 4 ops
// Projection: 8 threads/token (2 channels each), weights smem-resident.
// Next x tile prefetched into registers during proj+scan.
// ---------------------------------------------------------------------------
__global__ __launch_bounds__(256, 4) void fused_kernel(
    const float* __restrict__ x,      // (NT, 8)
    const float* __restrict__ h0,     // (16,16) [d][s]
    const float* __restrict__ in_w,   // (32, 8)
    const float* __restrict__ dt_w,   // (16,16)
    const float* __restrict__ dt_b,   // (16,)
    const float* __restrict__ B_w,    // (16,16)
    const float* __restrict__ C_w,    // (16,16)
    const float* __restrict__ A_log,  // (16,16) [d][s]
    const float* __restrict__ Dp,     // (16,)
    const float* __restrict__ rope,   // (16,16) [d][s]
    const float* __restrict__ Wout,   // (8,16)
    float* __restrict__ out,          // (NT, 8)
    float* __restrict__ hfin)         // 256 floats or nullptr
{
    __shared__ float  s_inw[32 * 9];        // padded stride 9
    __shared__ float  s_dtw[16 * 20];       // padded stride 20 (float4-ok)
    __shared__ float  s_bw [16 * 20];
    __shared__ float  s_cw [16 * 20];
    __shared__ float  s_dtb[16], s_Dp[16];
    __shared__ float  s_wo [8 * 16];        // stride 16 (float4 loads)
    __shared__ float  s_x  [2][TT * 8];     // double-buffered x tile
    __shared__ float  s_xbv[TT * 20];       // xb exchange, stride 20
    __shared__ float4 s_dd [TT * 8];        // (dt,dtxb)x2   [tok][jpair]
    __shared__ float4 s_gt [TT * 8];        // (gz,Dxb)x2    [tok][jpair]
    __shared__ float4 s_bc [TT * 8];        // (B,C)x2       [tok][spair]
    __shared__ float  s_hc [TT * 128];      // per-step partials [i][tid<128]
    __shared__ float  s_yf [TT * 16];       // gated y       [i][d]

    const unsigned FULL = 0xffffffffu;
    int tid  = threadIdx.x;
    int lane = tid & 31;

    // ---- weights to smem ----
    s_dtw[(tid >> 4) * 20 + (tid & 15)] = dt_w[tid];
    s_bw [(tid >> 4) * 20 + (tid & 15)] = B_w[tid];
    s_cw [(tid >> 4) * 20 + (tid & 15)] = C_w[tid];
    s_inw[(tid >> 3) * 9 + (tid & 7)]   = in_w[tid & 255];
    if (tid < 128) s_wo[tid] = Wout[tid];
    if (tid < 16) { s_dtb[tid] = dt_b[tid]; s_Dp[tid] = Dp[tid]; }

    int k     = blockIdx.x;
    int start = (int)(((long long)k       * NT) / NCH);
    int end   = (int)(((long long)(k + 1) * NT) / NCH);
    int begin = (k == 0) ? 0 : (start - WUP);

    // ---- scan state: 2 states per thread (tid < 128) ----
    int d  = tid >> 3;           // 0..15
    int sp = tid & 7;            // s-pair: states 2sp, 2sp+1
    int srcLane = (lane & 24) | ((sp + 7) & 7);   // neighbor sp-1 in 8-lane group
    float mAh_e = 0.f, mAh_o = 0.f, rf_e = 0.f, rf_o = 0.f, h_e = 0.f, h_o = 0.f;
    if (tid < 128) {
        int se = d * 16 + 2 * sp;
        mAh_e = 0.5f * __expf(A_log[se]);
        mAh_o = 0.5f * __expf(A_log[se + 1]);
        rf_e  = rope[se];
        rf_o  = rope[se + 1];
        if (k == 0) { h_e = h0[se]; h_o = h0[se + 1]; }
    }

    int nsteps = end - begin;
    int ntiles = (nsteps + TT - 1) / TT;

    // projection roles: 8 threads/token, 2 channels each
    int tok = tid >> 3;          // 0..31
    int r2  = tid & 7;           // channels j = 2r2, 2r2+1

    {   // prologue: stage x tile 0
        long gidx = (long)begin * 8 + tid;
        if (gidx >= (long)NT * 8) gidx = (long)NT * 8 - 1;
        s_x[0][tid] = x[gidx];
    }

    const float2* const sdd2 = (const float2*)s_dd;      // [i*16 + d]
    const float2* const sgt2 = (const float2*)s_gt;      // [i*16 + d]

    for (int tl = 0; tl < ntiles; ++tl) {
        int cur  = tl & 1;
        int tb   = begin + tl * TT;
        int tmax = min(TT, end - tb);
        int lim1 = min(max(start - tb, 0), tmax);

        __syncthreads();   // s_x[cur] ready; previous epilogue reads complete

        // prefetch next x tile into a register (lands during proj + scan)
        float xpre;
        {
            long gidx = (long)(tb + TT) * 8 + tid;
            if (gidx >= (long)NT * 8) gidx = (long)NT * 8 - 1;
            xpre = x[gidx];
        }

        // ---- P1: xb, z for my 2 channels ----
        float xv[8];
#pragma unroll
        for (int i = 0; i < 8; i++) xv[i] = s_x[cur][tok * 8 + i];
        float xb2[2], z2[2];
#pragma unroll
        for (int q = 0; q < 2; q++) {
            int j = 2 * r2 + q;
            const float* wa = s_inw + j * 9;
            const float* wz = s_inw + (j + 16) * 9;
            float a = wa[0] * xv[0], b = wz[0] * xv[0];
#pragma unroll
            for (int i = 1; i < 8; i++) {
                a = fmaf(wa[i], xv[i], a);
                b = fmaf(wz[i], xv[i], b);
            }
            xb2[q] = a;
            z2[q]  = b;
        }
        *(float2*)(s_xbv + tok * 20 + 2 * r2) = make_float2(xb2[0], xb2[1]);
        __syncthreads();

        // ---- P2: dt/B/C + activations for my 2 channels ----
        float xg[16];
#pragma unroll
        for (int q = 0; q < 4; q++) {
            float4 v = *(const float4*)(s_xbv + tok * 20 + q * 4);
            xg[q*4+0] = v.x; xg[q*4+1] = v.y; xg[q*4+2] = v.z; xg[q*4+3] = v.w;
        }
        float dt2[2], gz2[2], B2[2], C2[2];
#pragma unroll
        for (int q = 0; q < 2; q++) {
            int j = 2 * r2 + q;
            float dacc = s_dtb[j], bacc = 0.f, cacc = 0.f;
#pragma unroll
            for (int p = 0; p < 4; p++) {
                float4 wd = *(const float4*)(s_dtw + j * 20 + p * 4);
                float4 wb = *(const float4*)(s_bw  + j * 20 + p * 4);
                float4 wc = *(const float4*)(s_cw  + j * 20 + p * 4);
                dacc = fmaf(wd.x, xg[p*4+0], dacc); dacc = fmaf(wd.y, xg[p*4+1], dacc);
                dacc = fmaf(wd.z, xg[p*4+2], dacc); dacc = fmaf(wd.w, xg[p*4+3], dacc);
                bacc = fmaf(wb.x, xg[p*4+0], bacc); bacc = fmaf(wb.y, xg[p*4+1], bacc);
                bacc = fmaf(wb.z, xg[p*4+2], bacc); bacc = fmaf(wb.w, xg[p*4+3], bacc);
                cacc = fmaf(wc.x, xg[p*4+0], cacc); cacc = fmaf(wc.y, xg[p*4+1], cacc);
                cacc = fmaf(wc.z, xg[p*4+2], cacc); cacc = fmaf(wc.w, xg[p*4+3], cacc);
            }
            dt2[q] = __logf(1.0f + __expf(dacc));        // softplus (bounded)
            float zh = 0.5f * z2[q];
            float th;
            asm("tanh.approx.f32 %0, %1;" : "=f"(th) : "f"(zh));
            gz2[q] = fmaf(zh, th, zh);                   // silu(z)
            B2[q]  = bacc;
            C2[q]  = cacc;
        }
        s_dd[tok * 8 + r2] = make_float4(dt2[0], dt2[0] * xb2[0],
                                         dt2[1], dt2[1] * xb2[1]);
        s_gt[tok * 8 + r2] = make_float4(gz2[0], s_Dp[2*r2]   * xb2[0],
                                         gz2[1], s_Dp[2*r2+1] * xb2[1]);
        s_bc[tok * 8 + r2] = make_float4(B2[0], C2[0], B2[1], C2[1]);
        __syncthreads();

        // ---- S: sequential scan (warps 0-3 only) ----
        if (tid < 128) {
            int i = 0;
#pragma unroll 4
            for (; i < lim1; i++) {      // warmup: no output
                float2 dd = sdd2[i * 16 + d];
                float hpo = __shfl_sync(FULL, h_o, srcLane);
                float den_e = fmaf(dd.x, mAh_e, 1.0f);
                float den_o = fmaf(dd.x, mAh_o, 1.0f);
                float re, ro;
                asm("rcp.approx.ftz.f32 %0, %1;" : "=f"(re) : "f"(den_e));
                asm("rcp.approx.ftz.f32 %0, %1;" : "=f"(ro) : "f"(den_o));
                float Ae = fmaf(2.0f, re, -1.0f);
                float Ao = fmaf(2.0f, ro, -1.0f);
                float ae = dd.x * rf_e, ao = dd.x * rf_o;
                float ae2 = ae * ae,    ao2 = ao * ao;
                float sne = ae * fmaf(ae2, -0.16666667f, 1.0f);
                float sno = ao * fmaf(ao2, -0.16666667f, 1.0f);
                float cse = fmaf(ae2, fmaf(ae2, 0.041666667f, -0.5f), 1.0f);
                float cso = fmaf(ao2, fmaf(ao2, 0.041666667f, -0.5f), 1.0f);
                float4 bc = s_bc[i * 8 + sp];
                float hre = fmaf(cse, h_e, -(sne * hpo));
                float hro = fmaf(cso, h_o, -(sno * h_e));  // old h_e
                h_e = fmaf(Ae, hre, dd.y * bc.x);
                h_o = fmaf(Ao, hro, dd.y * bc.z);
            }
#pragma unroll 4
            for (; i < tmax; i++) {      // output region
                float2 dd = sdd2[i * 16 + d];
                float hpo = __shfl_sync(FULL, h_o, srcLane);
                float den_e = fmaf(dd.x, mAh_e, 1.0f);
                float den_o = fmaf(dd.x, mAh_o, 1.0f);
                float re, ro;
                asm("rcp.approx.ftz.f32 %0, %1;" : "=f"(re) : "f"(den_e));
                asm("rcp.approx.ftz.f32 %0, %1;" : "=f"(ro) : "f"(den_o));
                float Ae = fmaf(2.0f, re, -1.0f);
                float Ao = fmaf(2.0f, ro, -1.0f);
                float ae = dd.x * rf_e, ao = dd.x * rf_o;
                float ae2 = ae * ae,    ao2 = ao * ao;
                float sne = ae * fmaf(ae2, -0.16666667f, 1.0f);
                float sno = ao * fmaf(ao2, -0.16666667f, 1.0f);
                float cse = fmaf(ae2, fmaf(ae2, 0.041666667f, -0.5f), 1.0f);
                float cso = fmaf(ao2, fmaf(ao2, 0.041666667f, -0.5f), 1.0f);
                float4 bc = s_bc[i * 8 + sp];
                float hre = fmaf(cse, h_e, -(sne * hpo));
                float hro = fmaf(cso, h_o, -(sno * h_e));
                h_e = fmaf(Ae, hre, dd.y * bc.x);
                h_o = fmaf(Ao, hro, dd.y * bc.z);
                s_hc[i * 128 + tid] = fmaf(h_e, bc.y, h_o * bc.w);
            }
        }
        __syncthreads();                 // scan done; s_hc complete

        // store prefetched x for next tile
        s_x[cur ^ 1][tid] = xpre;

        // ---- E1: reduce 8 partials + gate -> s_yf ----
#pragma unroll
        for (int q = 0; q < 2; q++) {
            int idx = q * 256 + tid;     // 0..511
            int ii = idx >> 4, dj = idx & 15;
            if (ii >= lim1 && ii < tmax) {
                const float4* hp4 = (const float4*)(s_hc + ii * 128 + dj * 8);
                float4 v0 = hp4[0], v1 = hp4[1];
                float p = ((v0.x + v0.y) + (v0.z + v0.w))
                        + ((v1.x + v1.y) + (v1.z + v1.w));
                float2 g = sgt2[ii * 16 + dj];           // (gz, Dxb)
                s_yf[ii * 16 + dj] = fmaf(p, g.x, g.y);
            }
        }
        __syncthreads();

        // ---- E2: out = yf @ Wout.T (coalesced stores) ----
        int nout = tmax - lim1;
        for (int t = tid; t < (nout << 3); t += 256) {
            int ii = lim1 + (t >> 3);
            int m  = t & 7;
            const float4* wr = (const float4*)(s_wo + m * 16);
            const float4* yr = (const float4*)(s_yf + (ii << 4));
            float acc = 0.f;
#pragma unroll
            for (int p = 0; p < 4; p++) {
                float4 w4 = wr[p], y4 = yr[p];
                acc = fmaf(w4.x, y4.x, acc); acc = fmaf(w4.y, y4.y, acc);
                acc = fmaf(w4.z, y4.z, acc); acc = fmaf(w4.w, y4.w, acc);
            }
            out[(long)(tb + ii) * 8 + m] = acc;
        }
    }

    if (k == NCH - 1 && tid < 128) {
        float* dst = hfin ? hfin : g_hdump;
        int se = d * 16 + 2 * sp;
        dst[se]     = h_e;               // exact final state
        dst[se + 1] = h_o;
    }
}

// ---------------------------------------------------------------------------
extern "C" void kernel_launch(void* const* d_in, const int* in_sizes, int n_in,
                              void* d_out, int out_size)
{
    const float* x    = (const float*)d_in[0];
    const float* h0   = (const float*)d_in[1];
    const float* inw  = (const float*)d_in[2];
    const float* dtw  = (const float*)d_in[3];
    const float* dtb  = (const float*)d_in[4];
    const float* Bw   = (const float*)d_in[5];
    const float* Cw   = (const float*)d_in[6];
    const float* Alog = (const float*)d_in[7];
    const float* Dp   = (const float*)d_in[8];
    const float* rope = (const float*)d_in[9];
    const float* Wout = (const float*)d_in[10];

    float* out  = (float*)d_out;
    float* hfin = (out_size >= NT * 8 + 256) ? (out + NT * 8) : nullptr;

    fused_kernel<<<NCH, 256>>>(x, h0, inw, dtw, dtb, Bw, Cw,
                               Alog, Dp, rope, Wout, out, hfin);
}